// round 2
// baseline (speedup 1.0000x reference)
#include <cuda_runtime.h>
#include <math.h>

// Problem constants
// B=8, T=512, N=128, F=16, H=32, L=4
#define BTNH_ 16777216ull   // 8*512*128*32

// Scratch (allocation-free: static device globals)
__device__ float g_xa[16777216];
__device__ float g_xb[16777216];
__device__ float g_xres[16777216];
__device__ float g_tcn[4ull * 16777216ull];

// ---------------------------------------------------------------------------
// K1: input projection  Xp = X @ in_w + in_b  -> split into x_a | x_b | x_res
// grid: 65536 blocks x 256 thr.  8 rows/block, 32 lanes/row (lane = out col o)
// ---------------------------------------------------------------------------
__global__ void __launch_bounds__(256) k_inproj(const float* __restrict__ X,
                                                const float* __restrict__ in_w,
                                                const float* __restrict__ in_b) {
    __shared__ float sw[1536];
    __shared__ float sb[96];
    for (int i = threadIdx.x; i < 1536; i += 256) sw[i] = in_w[i];
    if (threadIdx.x < 96) sb[threadIdx.x] = in_b[threadIdx.x];
    __syncthreads();

    int row = blockIdx.x * 8 + (threadIdx.x >> 5);
    int o = threadIdx.x & 31;
    const float4* xr = (const float4*)(X + (size_t)row * 16);
    float4 v0 = xr[0], v1 = xr[1], v2 = xr[2], v3 = xr[3];
    float x[16] = {v0.x, v0.y, v0.z, v0.w, v1.x, v1.y, v1.z, v1.w,
                   v2.x, v2.y, v2.z, v2.w, v3.x, v3.y, v3.z, v3.w};
    float a0 = sb[o], a1 = sb[32 + o], a2 = sb[64 + o];
#pragma unroll
    for (int f = 0; f < 16; f++) {
        float xv = x[f];
        a0 = fmaf(xv, sw[f * 96 + o], a0);
        a1 = fmaf(xv, sw[f * 96 + 32 + o], a1);
        a2 = fmaf(xv, sw[f * 96 + 64 + o], a2);
    }
    size_t p = (size_t)row * 32 + o;
    g_xa[p] = a0;
    g_xb[p] = a1;
    g_xres[p] = a2;
}

// ---------------------------------------------------------------------------
// K2: all 4 layers' gated dilated causal convs.
// One block per bn (B*N = 1024 blocks), 512 threads (one per tau).
// Both sequences (x_a, x_b) staged in padded smem (stride 33 -> conflict-free
// scalar reads). Staging stores are SCALAR: stride-33 rows are only 4B-aligned,
// so float4 STS would be misaligned (this was the round-1 trap).
// Writes tcn in the final [B,T,N,H] layout (reshape+transpose applied here).
// ---------------------------------------------------------------------------
__global__ void __launch_bounds__(512) k_conv(const float* __restrict__ ct_w,
                                              const float* __restrict__ ct_b,
                                              const float* __restrict__ cs_w,
                                              const float* __restrict__ cs_b) {
    extern __shared__ float sm2[];
    float* sxa = sm2;            // 512*33 = 16896
    float* sxb = sm2 + 16896;    // 16896
    float* swa = sm2 + 33792;    // 2048 (ct_w[l]: [2][32][32])
    float* swb = sm2 + 35840;    // 2048
    float* sba = sm2 + 37888;    // 32
    float* sbb = sm2 + 37920;    // 32

    int tid = threadIdx.x;
    int bn = blockIdx.x;
    const float* xa = g_xa + (size_t)bn * 16384;
    const float* xb = g_xb + (size_t)bn * 16384;
    for (int i = tid; i < 4096; i += 512) {
        float4 va = ((const float4*)xa)[i];
        float4 vb = ((const float4*)xb)[i];
        int tt = i >> 3, c0 = (i & 7) * 4;
        float* pa = &sxa[tt * 33 + c0];
        float* pb = &sxb[tt * 33 + c0];
        pa[0] = va.x; pa[1] = va.y; pa[2] = va.z; pa[3] = va.w;
        pb[0] = vb.x; pb[1] = vb.y; pb[2] = vb.z; pb[3] = vb.w;
    }

    int tau = tid;
    int b = bn >> 7, n = bn & 127;
    float stash[32];

    for (int l = 0; l < 4; l++) {
        __syncthreads();  // covers initial seq load + weight reuse across layers
        for (int i = tid; i < 2048; i += 512) {
            swa[i] = ct_w[l * 2048 + i];
            swb[i] = cs_w[l * 2048 + i];
        }
        if (tid < 32) {
            sba[tid] = ct_b[l * 32 + tid];
            sbb[tid] = cs_b[l * 32 + tid];
        }
        __syncthreads();
        int d = 1 << l;
        bool hp = (tau >= d);

        // conv_a -> tanh -> stash
        {
            float acc[32];
#pragma unroll
            for (int o = 0; o < 32; o++) acc[o] = sba[o];
            const float* cur = &sxa[tau * 33];
            const float* prv = &sxa[(tau - d) * 33];
#pragma unroll 4
            for (int c = 0; c < 32; c++) {
                float x1 = cur[c];
                float x0 = hp ? prv[c] : 0.f;
                const float* w0 = &swa[c * 32];
                const float* w1 = &swa[1024 + c * 32];
#pragma unroll
                for (int o = 0; o < 32; o++)
                    acc[o] = fmaf(w0[o], x0, fmaf(w1[o], x1, acc[o]));
            }
#pragma unroll
            for (int o = 0; o < 32; o++) {
                float t = __expf(-2.f * fabsf(acc[o]));
                float r = (1.f - t) / (1.f + t);
                stash[o] = copysignf(r, acc[o]);
            }
        }
        // conv_b -> sigmoid -> gate -> scatter write
        {
            float acc[32];
#pragma unroll
            for (int o = 0; o < 32; o++) acc[o] = sbb[o];
            const float* cur = &sxb[tau * 33];
            const float* prv = &sxb[(tau - d) * 33];
#pragma unroll 4
            for (int c = 0; c < 32; c++) {
                float x1 = cur[c];
                float x0 = hp ? prv[c] : 0.f;
                const float* w0 = &swb[c * 32];
                const float* w1 = &swb[1024 + c * 32];
#pragma unroll
                for (int o = 0; o < 32; o++)
                    acc[o] = fmaf(w0[o], x0, fmaf(w1[o], x1, acc[o]));
            }
#pragma unroll
            for (int o = 0; o < 32; o++) {
                float s = 1.f / (1.f + __expf(-acc[o]));
                acc[o] = stash[o] * s;
            }
            // tcn_final[b, tau, n, :] = gated value   (reshape+transpose folded in)
            float* outp =
                g_tcn + (size_t)l * BTNH_ + ((size_t)((b * 512 + tau) * 128 + n)) * 32;
#pragma unroll
            for (int o4 = 0; o4 < 8; o4++)
                ((float4*)outp)[o4] = make_float4(acc[4 * o4], acc[4 * o4 + 1],
                                                  acc[4 * o4 + 2], acc[4 * o4 + 3]);
        }
    }
}

// ---------------------------------------------------------------------------
// K3: fused 4-layer GCN/residual/skip recurrence + output head.
// One block per (b,t) pair (4096 blocks), 256 threads = 8 warps.
// Warp g owns rows [g*16, g*16+16); lane = output channel o.
// smem: A [128x128], x_res [128x32], warp-private staging buffer [128x32].
// skip accumulator lives in registers.
// ---------------------------------------------------------------------------
__global__ void __launch_bounds__(256, 2) k_layers(
    const float* __restrict__ A, const float* __restrict__ gcn_w,
    const float* __restrict__ gcn_b, const float* __restrict__ res_w,
    const float* __restrict__ res_b, const float* __restrict__ skip_w,
    const float* __restrict__ skip_b, const float* __restrict__ out1_w,
    const float* __restrict__ out1_b, const float* __restrict__ out2_w,
    const float* __restrict__ out2_b, float* __restrict__ out) {
    extern __shared__ float sm3[];
    float* sA = sm3;            // 16384
    float* sX = sm3 + 16384;    // 4096  (x_res tile)
    float* sB = sm3 + 20480;    // 4096  (warp-private staging: AX -> h -> head)

    int bt = blockIdx.x;  // b = bt/512, t = bt%512; base offset = bt*4096
    int tid = threadIdx.x;
    int g = tid >> 5;
    int o = tid & 31;
    int row0 = g * 16;
    size_t base = (size_t)bt * 4096;

    for (int i = tid; i < 4096; i += 256) ((float4*)sA)[i] = ((const float4*)A)[i];
    for (int i = tid; i < 1024; i += 256)
        ((float4*)sX)[i] = ((const float4*)(g_xres + base))[i];
    __syncthreads();

    float skip[16];
#pragma unroll
    for (int ii = 0; ii < 16; ii++) skip[ii] = 0.f;

    for (int l = 0; l < 4; l++) {
        // ---- A-mix: AX[i][o] = sum_j A[i][j] * Xres[j][o] ----
        float acc[16];
#pragma unroll
        for (int ii = 0; ii < 16; ii++) acc[ii] = 0.f;
#pragma unroll 2
        for (int j = 0; j < 128; j += 4) {
            float x0 = sX[(j + 0) * 32 + o];
            float x1 = sX[(j + 1) * 32 + o];
            float x2 = sX[(j + 2) * 32 + o];
            float x3 = sX[(j + 3) * 32 + o];
#pragma unroll
            for (int ii = 0; ii < 16; ii++) {
                float4 a = *(const float4*)&sA[(row0 + ii) * 128 + j];
                acc[ii] = fmaf(a.x, x0, fmaf(a.y, x1, fmaf(a.z, x2, fmaf(a.w, x3, acc[ii]))));
            }
        }
#pragma unroll
        for (int ii = 0; ii < 16; ii++) sB[(row0 + ii) * 32 + o] = acc[ii];
        __syncwarp();

        // ---- gcn + tcn -> h ----
        float w[32];
#pragma unroll
        for (int c = 0; c < 32; c++) w[c] = __ldg(&gcn_w[l * 1024 + c * 32 + o]);
        float bq = __ldg(&gcn_b[l * 32 + o]);
        const float* tcnp = g_tcn + (size_t)l * BTNH_ + base;
        float h[16];
#pragma unroll
        for (int ii = 0; ii < 16; ii++) {
            float s = bq;
            const float* rowp = &sB[(row0 + ii) * 32];
#pragma unroll
            for (int c4 = 0; c4 < 8; c4++) {
                float4 v = *(const float4*)&rowp[c4 * 4];
                s = fmaf(v.x, w[4 * c4 + 0],
                    fmaf(v.y, w[4 * c4 + 1],
                    fmaf(v.z, w[4 * c4 + 2], fmaf(v.w, w[4 * c4 + 3], s))));
            }
            h[ii] = s + tcnp[(row0 + ii) * 32 + o];
        }
        __syncwarp();
#pragma unroll
        for (int ii = 0; ii < 16; ii++) sB[(row0 + ii) * 32 + o] = h[ii];
        __syncwarp();

        // ---- skip += h @ skip_w + skip_b ----
#pragma unroll
        for (int c = 0; c < 32; c++) w[c] = __ldg(&skip_w[l * 1024 + c * 32 + o]);
        float bs = __ldg(&skip_b[l * 32 + o]);
#pragma unroll
        for (int ii = 0; ii < 16; ii++) {
            float s = bs;
            const float* rowp = &sB[(row0 + ii) * 32];
#pragma unroll
            for (int c4 = 0; c4 < 8; c4++) {
                float4 v = *(const float4*)&rowp[c4 * 4];
                s = fmaf(v.x, w[4 * c4 + 0],
                    fmaf(v.y, w[4 * c4 + 1],
                    fmaf(v.z, w[4 * c4 + 2], fmaf(v.w, w[4 * c4 + 3], s))));
            }
            skip[ii] += s;
        }

        // ---- x_res = h @ res_w + res_b + x_res ----
#pragma unroll
        for (int c = 0; c < 32; c++) w[c] = __ldg(&res_w[l * 1024 + c * 32 + o]);
        float br = __ldg(&res_b[l * 32 + o]);
        float xn[16];
#pragma unroll
        for (int ii = 0; ii < 16; ii++) {
            float s = br;
            const float* rowp = &sB[(row0 + ii) * 32];
#pragma unroll
            for (int c4 = 0; c4 < 8; c4++) {
                float4 v = *(const float4*)&rowp[c4 * 4];
                s = fmaf(v.x, w[4 * c4 + 0],
                    fmaf(v.y, w[4 * c4 + 1],
                    fmaf(v.z, w[4 * c4 + 2], fmaf(v.w, w[4 * c4 + 3], s))));
            }
            xn[ii] = s + sX[(row0 + ii) * 32 + o];
        }
        __syncthreads();  // all warps finished A-mix reads of sX
#pragma unroll
        for (int ii = 0; ii < 16; ii++) sX[(row0 + ii) * 32 + o] = xn[ii];
        __syncthreads();  // sX update visible to all warps for next layer
    }

    // ---- head: relu(skip) @ out1_w -> relu -> @ out2_w ----
#pragma unroll
    for (int ii = 0; ii < 16; ii++)
        sB[(row0 + ii) * 32 + o] = fmaxf(skip[ii], 0.f);
    __syncwarp();

    float w1r[32];
#pragma unroll
    for (int c = 0; c < 32; c++) w1r[c] = __ldg(&out1_w[c * 32 + o]);
    float b1 = __ldg(&out1_b[o]);
    float h2[16];
#pragma unroll
    for (int ii = 0; ii < 16; ii++) {
        float s = b1;
        const float* rowp = &sB[(row0 + ii) * 32];
#pragma unroll
        for (int c4 = 0; c4 < 8; c4++) {
            float4 v = *(const float4*)&rowp[c4 * 4];
            s = fmaf(v.x, w1r[4 * c4 + 0],
                fmaf(v.y, w1r[4 * c4 + 1],
                fmaf(v.z, w1r[4 * c4 + 2], fmaf(v.w, w1r[4 * c4 + 3], s))));
        }
        h2[ii] = fmaxf(s, 0.f);
    }
    __syncwarp();
#pragma unroll
    for (int ii = 0; ii < 16; ii++) sB[(row0 + ii) * 32 + o] = h2[ii];
    __syncwarp();

    if (o < 16) {
        float w2r[32];
#pragma unroll
        for (int c = 0; c < 32; c++) w2r[c] = __ldg(&out2_w[c * 16 + o]);
        float b2 = __ldg(&out2_b[o]);
        float* op = out + (size_t)bt * 2048;  // 128*16 per (b,t)
#pragma unroll
        for (int ii = 0; ii < 16; ii++) {
            float s = b2;
            const float* rowp = &sB[(row0 + ii) * 32];
#pragma unroll
            for (int c4 = 0; c4 < 8; c4++) {
                float4 v = *(const float4*)&rowp[c4 * 4];
                s = fmaf(v.x, w2r[4 * c4 + 0],
                    fmaf(v.y, w2r[4 * c4 + 1],
                    fmaf(v.z, w2r[4 * c4 + 2], fmaf(v.w, w2r[4 * c4 + 3], s))));
            }
            op[(row0 + ii) * 16 + o] = s;
        }
    }
}

// ---------------------------------------------------------------------------
extern "C" void kernel_launch(void* const* d_in, const int* in_sizes, int n_in,
                              void* d_out, int out_size) {
    const float* X = (const float*)d_in[0];
    const float* A = (const float*)d_in[1];
    const float* in_w = (const float*)d_in[2];
    const float* in_b = (const float*)d_in[3];
    const float* ct_w = (const float*)d_in[4];
    const float* ct_b = (const float*)d_in[5];
    const float* cs_w = (const float*)d_in[6];
    const float* cs_b = (const float*)d_in[7];
    const float* gcn_w = (const float*)d_in[8];
    const float* gcn_b = (const float*)d_in[9];
    const float* res_w = (const float*)d_in[10];
    const float* res_b = (const float*)d_in[11];
    const float* skip_w = (const float*)d_in[12];
    const float* skip_b = (const float*)d_in[13];
    const float* out1_w = (const float*)d_in[14];
    const float* out1_b = (const float*)d_in[15];
    const float* out2_w = (const float*)d_in[16];
    const float* out2_b = (const float*)d_in[17];
    float* out = (float*)d_out;

    // raise dynamic smem limits (idempotent, not a stream op)
    cudaFuncSetAttribute(k_conv, cudaFuncAttributeMaxDynamicSharedMemorySize,
                         37952 * 4);
    cudaFuncSetAttribute(k_layers, cudaFuncAttributeMaxDynamicSharedMemorySize,
                         24576 * 4);

    k_inproj<<<65536, 256>>>(X, in_w, in_b);
    k_conv<<<1024, 512, 37952 * 4>>>(ct_w, ct_b, cs_w, cs_b);
    k_layers<<<4096, 256, 24576 * 4>>>(A, gcn_w, gcn_b, res_w, res_b, skip_w,
                                       skip_b, out1_w, out1_b, out2_w, out2_b,
                                       out);
}